// round 1
// baseline (speedup 1.0000x reference)
#include <cuda_runtime.h>
#include <cstdint>

// Problem constants
#define NB 2
#define DIN 65
#define DD 4225          // 65*65
#define DDD 274625       // 65^3
#define DG 32            // conv1 output grid
#define G3 32768         // 32^3
#define C2 32
#define CO 100
#define COP 128          // padded out channels for conv3
#define CLS_CAP 71874    // max actives per parity class (2*33^3)

// ---------------- device globals (no allocation allowed) ----------------
__device__ float g_h1[NB * G3 * C2];        // NDHWC
__device__ float g_h2[NB * G3 * C2];        // NDHWC
__device__ float g_m1[NB * G3];
__device__ float g_w1T[27 * 32];            // [k][c]
__device__ float g_w2T[27 * 32 * 32];       // [k][ci][co]
__device__ float g_wI [27 * 32 * COP];      // [k][ci][co padded to 128]
__device__ float g_bn [4 * 32];             // A1,B1,A2,B2
__device__ int   g_cnt[8];
__device__ int   g_list[8 * CLS_CAP];

// ---------------- prep: BN fold, weight transposes, counters ----------------
__global__ void prep_kernel(const float* __restrict__ W1, const float* __restrict__ b1,
                            const float* __restrict__ g1, const float* __restrict__ bt1,
                            const float* __restrict__ rm1, const float* __restrict__ rv1,
                            const float* __restrict__ W2, const float* __restrict__ b2,
                            const float* __restrict__ g2, const float* __restrict__ bt2,
                            const float* __restrict__ rm2, const float* __restrict__ rv2,
                            const float* __restrict__ Winv) {
    int t = blockIdx.x * blockDim.x + threadIdx.x;
    if (t < 32) {
        float A1 = g1[t] * rsqrtf(rv1[t] + 1e-5f);
        g_bn[t]      = A1;
        g_bn[32 + t] = bt1[t] + (b1[t] - rm1[t]) * A1;
        float A2 = g2[t] * rsqrtf(rv2[t] + 1e-5f);
        g_bn[64 + t] = A2;
        g_bn[96 + t] = bt2[t] + (b2[t] - rm2[t]) * A2;
    }
    if (t < 8) g_cnt[t] = 0;
    if (t < 864) {                              // W1: [c][k] -> [k][c]
        int c = t / 27, k = t % 27;
        g_w1T[k * 32 + c] = W1[t];
    }
    if (t < 27648) {                            // W2: [co][ci][k] -> [k][ci][co]
        int co = t / 864, ci = (t / 27) % 32, k = t % 27;
        g_w2T[(k * 32 + ci) * 32 + co] = W2[t];
    }
    if (t < 27 * 32 * COP) {                    // Winv: [co][ci][k] -> [k][ci][co pad 128]
        int k = t / (32 * COP), ci = (t / COP) % 32, co = t % COP;
        g_wI[t] = (co < CO) ? Winv[(co * 32 + ci) * 27 + k] : 0.0f;
    }
}

// ---------------- conv1 (1->32, k3, s2, VALID) + BN + ReLU + mask ----------------
__global__ void __launch_bounds__(256) conv1_kernel(const float* __restrict__ x,
                                                    const int* __restrict__ m0) {
    __shared__ float sw[27 * 32];
    __shared__ float sA[32], sB[32];
    int tid = threadIdx.x;
    for (int i = tid; i < 864; i += 256) sw[i] = g_w1T[i];
    if (tid < 32) { sA[tid] = g_bn[tid]; sB[tid] = g_bn[32 + tid]; }
    __syncthreads();

    int t = blockIdx.x * 256 + tid;            // ((b*32+z)*32+y)*32+x
    int b = t >> 15, z = (t >> 10) & 31, y = (t >> 5) & 31, xx = t & 31;
    const float* xb = x + b * DDD;
    const int*   mb = m0 + b * DDD;

    float acc[32];
#pragma unroll
    for (int c = 0; c < 32; c++) acc[c] = 0.0f;
    int cnt = 0;

#pragma unroll
    for (int kz = 0; kz < 3; kz++)
#pragma unroll
        for (int ky = 0; ky < 3; ky++)
#pragma unroll
            for (int kx = 0; kx < 3; kx++) {
                int idx = (2 * z + kz) * DD + (2 * y + ky) * DIN + (2 * xx + kx);
                cnt += mb[idx];
                float xv = xb[idx];
                int k = (kz * 3 + ky) * 3 + kx;
                if (xv != 0.0f) {
#pragma unroll
                    for (int c = 0; c < 32; c++) acc[c] += sw[k * 32 + c] * xv;
                }
            }

    float m = (cnt > 0) ? 1.0f : 0.0f;
    g_m1[t] = m;
    int o = t * 32;
#pragma unroll
    for (int c = 0; c < 32; c++) {
        float v = fmaxf(acc[c] * sA[c] + sB[c], 0.0f) * m;
        g_h1[o + c] = v;
    }
}

// ---------------- conv2 (32->32, k3, SAME) + BN + ReLU + mask ----------------
// block tile: 4z x 8y x 8x = 256 voxels, 32 co. 256 threads, thread = 4co x 8vox.
#define CHP 36   // padded channel stride in smem halo
__global__ void __launch_bounds__(256) conv2_kernel() {
    extern __shared__ float sa[];              // [6*10*10][CHP]
    int tid = threadIdx.x;
    int bid = blockIdx.x;
    int b  = bid >> 7;
    int z0 = ((bid >> 4) & 7) * 4;
    int y0 = ((bid >> 2) & 3) * 8;
    int x0 = (bid & 3) * 8;

    // cooperative halo load: 600 positions x 32 ch (float4 granules)
    for (int s = tid; s < 4800; s += 256) {
        int pos = s >> 3, q = (s & 7) * 4;
        int hz = pos / 100, hy = (pos / 10) % 10, hx = pos % 10;
        int gz = z0 + hz - 1, gy = y0 + hy - 1, gx = x0 + hx - 1;
        float4 v = make_float4(0.f, 0.f, 0.f, 0.f);
        if ((unsigned)gz < 32u && (unsigned)gy < 32u && (unsigned)gx < 32u)
            v = *(const float4*)&g_h1[(((b * 32 + gz) * 32 + gy) * 32 + gx) * 32 + q];
        *(float4*)&sa[pos * CHP + q] = v;
    }
    __syncthreads();

    int cg = tid & 7, co0 = cg * 4;
    int vg = tid >> 3;                          // 0..31
    int zz = vg >> 3, yy = vg & 7;              // local z(0..3), y(0..7)

    float4 acc[8];
#pragma unroll
    for (int j = 0; j < 8; j++) acc[j] = make_float4(0.f, 0.f, 0.f, 0.f);

#pragma unroll
    for (int kz = 0; kz < 3; kz++)
#pragma unroll
        for (int ky = 0; ky < 3; ky++)
#pragma unroll
            for (int kx = 0; kx < 3; kx++) {
                const float* ap = &sa[((zz + kz) * 100 + (yy + ky) * 10 + kx) * CHP];
                const float4* wp =
                    (const float4*)&g_w2T[(((kz * 3 + ky) * 3 + kx) * 32) * 32 + co0];
#pragma unroll 4
                for (int ci = 0; ci < 32; ci++) {
                    float4 w = __ldg(wp + ci * 8);
#pragma unroll
                    for (int j = 0; j < 8; j++) {
                        float a = ap[j * CHP + ci];
                        acc[j].x += a * w.x; acc[j].y += a * w.y;
                        acc[j].z += a * w.z; acc[j].w += a * w.w;
                    }
                }
            }

    float4 A2 = *(const float4*)&g_bn[64 + co0];
    float4 B2 = *(const float4*)&g_bn[96 + co0];
    int gz = z0 + zz, gy = y0 + yy;
#pragma unroll
    for (int j = 0; j < 8; j++) {
        int vox = ((b * 32 + gz) * 32 + gy) * 32 + (x0 + j);
        float m = g_m1[vox];
        float4 r;
        r.x = fmaxf(acc[j].x * A2.x + B2.x, 0.f) * m;
        r.y = fmaxf(acc[j].y * A2.y + B2.y, 0.f) * m;
        r.z = fmaxf(acc[j].z * A2.z + B2.z, 0.f) * m;
        r.w = fmaxf(acc[j].w * A2.w + B2.w, 0.f) * m;
        *(float4*)&g_h2[vox * 32 + co0] = r;
    }
}

// ---------------- zero-fill output ----------------
__global__ void fill_kernel(float4* __restrict__ out, int n4) {
    int t = blockIdx.x * 256 + threadIdx.x;
    if (t < n4) out[t] = make_float4(0.f, 0.f, 0.f, 0.f);
}

// ---------------- active-voxel list by parity class ----------------
__global__ void buildlist_kernel(const int* __restrict__ m0) {
    int t = blockIdx.x * 256 + threadIdx.x;
    if (t >= NB * DDD) return;
    if (m0[t] == 0) return;
    int b = t / DDD, r = t % DDD;
    int z = r / DD, y = (r / DIN) % DIN, x = r % DIN;
    int cls = ((z & 1) << 2) | ((y & 1) << 1) | (x & 1);
    int pos = atomicAdd(&g_cnt[cls], 1);
    g_list[cls * CLS_CAP + pos] = (b << 21) | (z << 14) | (y << 7) | x;
}

// ---------------- conv3: transposed conv via per-parity-class GEMM ----------------
// block: 64 active voxels of one class x 128 (padded) out ch; 256 threads = 32cg x 8vg,
// thread tile = 4co x 8vox.
__global__ void __launch_bounds__(256) convinv_kernel(float* __restrict__ out,
                                                      const float* __restrict__ binv) {
    int cls = blockIdx.y;
    int n = g_cnt[cls];
    int v0 = blockIdx.x * 64;
    if (v0 >= n) return;
    int vc = min(64, n - v0);

    int pz = (cls >> 2) & 1, py = (cls >> 1) & 1, px = cls & 1;
    int nz = pz ? 1 : 2, ny = py ? 1 : 2, nx = px ? 1 : 2;
    int T = nz * ny * nx;
    int T32 = T * 32;

    extern __shared__ float sm[];
    float* sact = sm;                       // [64][T][32]
    int* slist = (int*)(sm + 64 * T32);     // [64]

    int tid = threadIdx.x;
    if (tid < 64) slist[tid] = (tid < vc) ? g_list[cls * CLS_CAP + v0 + tid] : 0;
    __syncthreads();

    // stage activations (zero-padded for invalid taps / missing voxels)
    int total = 64 * T32;
    for (int s = tid; s < total; s += 256) {
        int v = s / T32, r = s - v * T32, tt = r >> 5, ci = r & 31;
        float val = 0.0f;
        if (v < vc) {
            int enc = slist[v];
            int b = enc >> 21, z = (enc >> 14) & 127, y = (enc >> 7) & 127, x = enc & 127;
            int tz = tt / (ny * nx), rr = tt % (ny * nx), ty = rr / nx, tx = rr % nx;
            int iz = (z >> 1) + (pz ? 0 : tz - 1);
            int iy = (y >> 1) + (py ? 0 : ty - 1);
            int ix = (x >> 1) + (px ? 0 : tx - 1);
            if ((unsigned)iz < 32u && (unsigned)iy < 32u && (unsigned)ix < 32u)
                val = g_h2[(((b * 32 + iz) * 32 + iy) * 32 + ix) * 32 + ci];
        }
        sact[s] = val;
    }
    __syncthreads();

    int cg = tid & 31, co0 = cg * 4;
    int vg = tid >> 5;                      // 0..7
    float4 acc[8];
#pragma unroll
    for (int j = 0; j < 8; j++) acc[j] = make_float4(0.f, 0.f, 0.f, 0.f);

    for (int tt = 0; tt < T; tt++) {
        int tz = tt / (ny * nx), rr = tt % (ny * nx), ty = rr / nx, tx = rr % nx;
        int kz = pz ? 1 : (tz ? 2 : 0);
        int ky = py ? 1 : (ty ? 2 : 0);
        int kx = px ? 1 : (tx ? 2 : 0);
        int k = (kz * 3 + ky) * 3 + kx;
        const float4* wp = (const float4*)&g_wI[k * 32 * COP + co0];
        const float* ap = &sact[(vg * 8) * T32 + tt * 32];
#pragma unroll 4
        for (int ci = 0; ci < 32; ci++) {
            float4 w = __ldg(wp + ci * (COP / 4));
#pragma unroll
            for (int j = 0; j < 8; j++) {
                float a = ap[j * T32 + ci];
                acc[j].x += a * w.x; acc[j].y += a * w.y;
                acc[j].z += a * w.z; acc[j].w += a * w.w;
            }
        }
    }

    float4 bv = make_float4(0.f, 0.f, 0.f, 0.f);
    if (co0 + 0 < CO) bv.x = binv[co0 + 0];
    if (co0 + 1 < CO) bv.y = binv[co0 + 1];
    if (co0 + 2 < CO) bv.z = binv[co0 + 2];
    if (co0 + 3 < CO) bv.w = binv[co0 + 3];

#pragma unroll
    for (int j = 0; j < 8; j++) {
        int v = vg * 8 + j;
        if (v >= vc) continue;
        int enc = slist[v];
        int b = enc >> 21, z = (enc >> 14) & 127, y = (enc >> 7) & 127, x = enc & 127;
        size_t base = (size_t)b * CO * DDD + (size_t)z * DD + (size_t)y * DIN + x;
        if (co0 + 0 < CO) out[base + (size_t)(co0 + 0) * DDD] = acc[j].x + bv.x;
        if (co0 + 1 < CO) out[base + (size_t)(co0 + 1) * DDD] = acc[j].y + bv.y;
        if (co0 + 2 < CO) out[base + (size_t)(co0 + 2) * DDD] = acc[j].z + bv.z;
        if (co0 + 3 < CO) out[base + (size_t)(co0 + 3) * DDD] = acc[j].w + bv.w;
    }
}

// ---------------- launch ----------------
extern "C" void kernel_launch(void* const* d_in, const int* in_sizes, int n_in,
                              void* d_out, int out_size) {
    const float* x    = (const float*)d_in[0];
    const int*   m0   = (const int*)  d_in[1];
    const float* W1   = (const float*)d_in[2];
    const float* b1   = (const float*)d_in[3];
    const float* g1   = (const float*)d_in[4];
    const float* bt1  = (const float*)d_in[5];
    const float* rm1  = (const float*)d_in[6];
    const float* rv1  = (const float*)d_in[7];
    const float* W2   = (const float*)d_in[8];
    const float* b2   = (const float*)d_in[9];
    const float* g2   = (const float*)d_in[10];
    const float* bt2  = (const float*)d_in[11];
    const float* rm2  = (const float*)d_in[12];
    const float* rv2  = (const float*)d_in[13];
    const float* Winv = (const float*)d_in[14];
    const float* binv = (const float*)d_in[15];
    float* out = (float*)d_out;

    cudaFuncSetAttribute(conv2_kernel, cudaFuncAttributeMaxDynamicSharedMemorySize,
                         600 * CHP * 4);
    cudaFuncSetAttribute(convinv_kernel, cudaFuncAttributeMaxDynamicSharedMemorySize,
                         64 * 8 * 32 * 4 + 64 * 4);

    prep_kernel<<<(27 * 32 * COP + 255) / 256, 256>>>(W1, b1, g1, bt1, rm1, rv1,
                                                      W2, b2, g2, bt2, rm2, rv2, Winv);
    conv1_kernel<<<256, 256>>>(x, m0);
    conv2_kernel<<<256, 256, 600 * CHP * 4>>>();

    int n4 = (NB * CO * DDD) / 4;   // 13,731,250
    fill_kernel<<<(n4 + 255) / 256, 256>>>((float4*)d_out, n4);
    buildlist_kernel<<<(NB * DDD + 255) / 256, 256>>>(m0);

    dim3 g3((CLS_CAP + 63) / 64, 8);
    convinv_kernel<<<g3, 256, 64 * 8 * 32 * 4 + 64 * 4>>>(out, binv);
}

// round 4
// speedup vs baseline: 1.0100x; 1.0100x over previous
#include <cuda_runtime.h>
#include <cstdint>

// Problem constants
#define NB 2
#define DIN 65
#define DD 4225          // 65*65
#define DDD 274625       // 65^3
#define G3 32768         // 32^3
#define C2 32
#define CO 100
#define COP 128          // padded out channels for conv3
#define CLS_CAP 71874    // max actives per parity class (2*33^3)
#define CHP 33           // smem halo channel stride (conflict-free: bank=(pos+ci)%32)

// ---------------- device globals ----------------
__device__ __align__(128) float g_h1[NB * G3 * C2];        // NDHWC
__device__ __align__(128) float g_h2[NB * G3 * C2];        // NDHWC
__device__ __align__(128) float g_m1[NB * G3];
__device__ __align__(128) float g_w1T[27 * 32];            // [k][c]
__device__ __align__(128) float g_w2T[27 * 32 * 32];       // [k][ci][co]
__device__ __align__(128) float g_wI [27 * 32 * COP];      // [k][ci][co pad 128]
__device__ __align__(128) float g_bn [4 * 32];             // A1,B1,A2,B2
__device__ int   g_cnt[8];
__device__ int   g_list[8 * CLS_CAP];

// ---------------- f32x2 packed-FMA helpers ----------------
__device__ __forceinline__ unsigned long long pk2(float a) {
    unsigned long long r;
    asm("mov.b64 %0, {%1, %1};" : "=l"(r) : "f"(a));
    return r;
}
__device__ __forceinline__ void fma2(unsigned long long& d, unsigned long long a,
                                     unsigned long long b) {
    asm("fma.rn.f32x2 %0, %1, %2, %0;" : "+l"(d) : "l"(a), "l"(b));
}
__device__ __forceinline__ float2 upk(unsigned long long v) {
    float2 r;
    asm("mov.b64 {%0, %1}, %2;" : "=f"(r.x), "=f"(r.y) : "l"(v));
    return r;
}

// ---------------- prep: BN fold, weight transposes, counters ----------------
__global__ void prep_kernel(const float* __restrict__ W1, const float* __restrict__ b1,
                            const float* __restrict__ g1, const float* __restrict__ bt1,
                            const float* __restrict__ rm1, const float* __restrict__ rv1,
                            const float* __restrict__ W2, const float* __restrict__ b2,
                            const float* __restrict__ g2, const float* __restrict__ bt2,
                            const float* __restrict__ rm2, const float* __restrict__ rv2,
                            const float* __restrict__ Winv) {
    int t = blockIdx.x * blockDim.x + threadIdx.x;
    if (t < 32) {
        float A1 = g1[t] * rsqrtf(rv1[t] + 1e-5f);
        g_bn[t]      = A1;
        g_bn[32 + t] = bt1[t] + (b1[t] - rm1[t]) * A1;
        float A2 = g2[t] * rsqrtf(rv2[t] + 1e-5f);
        g_bn[64 + t] = A2;
        g_bn[96 + t] = bt2[t] + (b2[t] - rm2[t]) * A2;
    }
    if (t < 8) g_cnt[t] = 0;
    if (t < 864) {                              // W1: [c][k] -> [k][c]
        int c = t / 27, k = t % 27;
        g_w1T[k * 32 + c] = W1[t];
    }
    if (t < 27648) {                            // W2: [co][ci][k] -> [k][ci][co]
        int co = t / 864, ci = (t / 27) % 32, k = t % 27;
        g_w2T[(k * 32 + ci) * 32 + co] = W2[t];
    }
    if (t < 27 * 32 * COP) {                    // Winv: [co][ci][k] -> [k][ci][co pad]
        int k = t / (32 * COP), ci = (t / COP) % 32, co = t % COP;
        g_wI[t] = (co < CO) ? Winv[(co * 32 + ci) * 27 + k] : 0.0f;
    }
}

// ---------------- conv1 (1->32, k3, s2, VALID) + BN + ReLU + mask ----------------
__global__ void __launch_bounds__(256) conv1_kernel(const float* __restrict__ x,
                                                    const int* __restrict__ m0) {
    __shared__ float sw[27 * 32];
    __shared__ float sA[32], sB[32];
    int tid = threadIdx.x;
    for (int i = tid; i < 864; i += 256) sw[i] = g_w1T[i];
    if (tid < 32) { sA[tid] = g_bn[tid]; sB[tid] = g_bn[32 + tid]; }
    __syncthreads();

    int t = blockIdx.x * 256 + tid;            // ((b*32+z)*32+y)*32+x
    int b = t >> 15, z = (t >> 10) & 31, y = (t >> 5) & 31, xx = t & 31;
    const float* xb = x + b * DDD;
    const int*   mb = m0 + b * DDD;

    float acc[32];
#pragma unroll
    for (int c = 0; c < 32; c++) acc[c] = 0.0f;
    int cnt = 0;

#pragma unroll
    for (int kz = 0; kz < 3; kz++)
#pragma unroll
        for (int ky = 0; ky < 3; ky++)
#pragma unroll
            for (int kx = 0; kx < 3; kx++) {
                int idx = (2 * z + kz) * DD + (2 * y + ky) * DIN + (2 * xx + kx);
                cnt += mb[idx];
                float xv = xb[idx];
                int k = (kz * 3 + ky) * 3 + kx;
                if (xv != 0.0f) {
#pragma unroll
                    for (int c = 0; c < 32; c++) acc[c] += sw[k * 32 + c] * xv;
                }
            }

    float m = (cnt > 0) ? 1.0f : 0.0f;
    g_m1[t] = m;
    int o = t * 32;
#pragma unroll
    for (int c = 0; c < 32; c++) {
        float v = fmaxf(acc[c] * sA[c] + sB[c], 0.0f) * m;
        g_h1[o + c] = v;
    }
}

// ---------------- conv2 (32->32, k3, SAME) + BN + ReLU + mask ----------------
// block tile: 4z x 8y x 8x = 256 voxels, 32 co. 256 threads.
// thread = 8co x 4vox, packed f32x2 accumulators (co pairs).
__global__ void __launch_bounds__(256) conv2_kernel() {
    extern __shared__ float sa[];              // [6*10*10][CHP]
    int tid = threadIdx.x;
    int bid = blockIdx.x;
    int b  = bid >> 7;
    int z0 = ((bid >> 4) & 7) * 4;
    int y0 = ((bid >> 2) & 3) * 8;
    int x0 = (bid & 3) * 8;

    // cooperative halo load: 600 positions x 32 ch
    for (int s = tid; s < 4800; s += 256) {
        int pos = s >> 3, q = (s & 7) * 4;
        int hz = pos / 100, hy = (pos / 10) % 10, hx = pos % 10;
        int gz = z0 + hz - 1, gy = y0 + hy - 1, gx = x0 + hx - 1;
        float4 v = make_float4(0.f, 0.f, 0.f, 0.f);
        if ((unsigned)gz < 32u && (unsigned)gy < 32u && (unsigned)gx < 32u)
            v = *(const float4*)&g_h1[(((b * 32 + gz) * 32 + gy) * 32 + gx) * 32 + q];
        float* d = &sa[pos * CHP + q];
        d[0] = v.x; d[1] = v.y; d[2] = v.z; d[3] = v.w;
    }
    __syncthreads();

    int cg = tid & 3, co0 = cg * 8;
    int vg = tid >> 2;                          // 0..63
    int zz = vg >> 4;                           // 0..3
    int yy = (vg >> 1) & 7;                     // 0..7
    int xh = (vg & 1) * 4;                      // 0 or 4

    unsigned long long acc[4][4];
#pragma unroll
    for (int j = 0; j < 4; j++)
#pragma unroll
        for (int p = 0; p < 4; p++) acc[j][p] = 0ull;

#pragma unroll 1
    for (int kz = 0; kz < 3; kz++)
#pragma unroll 1
        for (int ky = 0; ky < 3; ky++)
#pragma unroll 1
            for (int kx = 0; kx < 3; kx++) {
                const float* ap = &sa[((zz + kz) * 100 + (yy + ky) * 10 + xh + kx) * CHP];
                const ulonglong2* wp =
                    (const ulonglong2*)&g_w2T[(((kz * 3 + ky) * 3 + kx) * 32) * 32 + co0];
#pragma unroll 4
                for (int ci = 0; ci < 32; ci++) {
                    ulonglong2 w01 = __ldg(wp + ci * 8);       // co0..co0+3
                    ulonglong2 w23 = __ldg(wp + ci * 8 + 1);   // co0+4..co0+7
#pragma unroll
                    for (int j = 0; j < 4; j++) {
                        unsigned long long a2 = pk2(ap[j * CHP + ci]);
                        fma2(acc[j][0], a2, w01.x);
                        fma2(acc[j][1], a2, w01.y);
                        fma2(acc[j][2], a2, w23.x);
                        fma2(acc[j][3], a2, w23.y);
                    }
                }
            }

    float4 Aa = *(const float4*)&g_bn[64 + co0];
    float4 Ab = *(const float4*)&g_bn[64 + co0 + 4];
    float4 Ba = *(const float4*)&g_bn[96 + co0];
    float4 Bb = *(const float4*)&g_bn[96 + co0 + 4];
    int gz = z0 + zz, gy = y0 + yy, gx0 = x0 + xh;
#pragma unroll
    for (int j = 0; j < 4; j++) {
        int vox = ((b * 32 + gz) * 32 + gy) * 32 + gx0 + j;
        float m = g_m1[vox];
        float2 v0 = upk(acc[j][0]), v1 = upk(acc[j][1]);
        float2 v2 = upk(acc[j][2]), v3 = upk(acc[j][3]);
        float4 r0, r1;
        r0.x = fmaxf(v0.x * Aa.x + Ba.x, 0.f) * m;
        r0.y = fmaxf(v0.y * Aa.y + Ba.y, 0.f) * m;
        r0.z = fmaxf(v1.x * Aa.z + Ba.z, 0.f) * m;
        r0.w = fmaxf(v1.y * Aa.w + Ba.w, 0.f) * m;
        r1.x = fmaxf(v2.x * Ab.x + Bb.x, 0.f) * m;
        r1.y = fmaxf(v2.y * Ab.y + Bb.y, 0.f) * m;
        r1.z = fmaxf(v3.x * Ab.z + Bb.z, 0.f) * m;
        r1.w = fmaxf(v3.y * Ab.w + Bb.w, 0.f) * m;
        *(float4*)&g_h2[vox * 32 + co0]     = r0;
        *(float4*)&g_h2[vox * 32 + co0 + 4] = r1;
    }
}

// ---------------- active-voxel list by parity class ----------------
__global__ void buildlist_kernel(const int* __restrict__ m0) {
    int t = blockIdx.x * 256 + threadIdx.x;
    if (t >= NB * DDD) return;
    if (m0[t] == 0) return;
    int b = t / DDD, r = t % DDD;
    int z = r / DD, y = (r / DIN) % DIN, x = r % DIN;
    int cls = ((z & 1) << 2) | ((y & 1) << 1) | (x & 1);
    int pos = atomicAdd(&g_cnt[cls], 1);
    g_list[cls * CLS_CAP + pos] = (b << 21) | (z << 14) | (y << 7) | x;
}

// ---------------- conv3: transposed conv via per-parity-class GEMM ----------------
// block: 64 active voxels x 128(pad) co; 256 thr = 16cg(8co) x 16vg(4vox). f32x2.
__global__ void __launch_bounds__(256) convinv_kernel(float* __restrict__ out,
                                                      const float* __restrict__ binv) {
    int cls = blockIdx.y;
    int n = g_cnt[cls];
    int pz = (cls >> 2) & 1, py = (cls >> 1) & 1, px = cls & 1;
    int nz = 2 - pz, ny = 2 - py, nx = 2 - px;
    int T = nz * ny * nx;
    int T32 = T * 32;
    int ST = T32 + 4;                       // padded stride (bank decorrelation)
    int tsh = 5 + (1 - pz) + (1 - py) + (1 - px);   // log2(T32)

    extern __shared__ float sm[];
    float* sact = sm;                       // [64][ST]
    int* slist = (int*)(sm + 64 * ST);      // [64]

    int tid = threadIdx.x;
    int cg = tid & 15, co0 = cg * 8;
    int vg = tid >> 4;                      // 0..15, 4 voxels each

    for (int v0 = blockIdx.x * 64; v0 < n; v0 += gridDim.x * 64) {
        int vc = min(64, n - v0);
        if (tid < 64) slist[tid] = (tid < vc) ? g_list[cls * CLS_CAP + v0 + tid] : 0;
        __syncthreads();

        int total = 64 * T32;
        for (int s = tid; s < total; s += 256) {
            int v = s >> tsh, r = s & (T32 - 1), tt = r >> 5, ci = r & 31;
            float val = 0.0f;
            if (v < vc) {
                int enc = slist[v];
                int b = enc >> 21, z = (enc >> 14) & 127, y = (enc >> 7) & 127, x = enc & 127;
                int tz = tt / (ny * nx), rr = tt % (ny * nx), ty = rr / nx, tx = rr % nx;
                int iz = (z >> 1) + (pz ? 0 : tz - 1);
                int iy = (y >> 1) + (py ? 0 : ty - 1);
                int ix = (x >> 1) + (px ? 0 : tx - 1);
                if ((unsigned)iz < 32u && (unsigned)iy < 32u && (unsigned)ix < 32u)
                    val = g_h2[(((b * 32 + iz) * 32 + iy) * 32 + ix) * 32 + ci];
            }
            sact[v * ST + tt * 32 + ci] = val;
        }
        __syncthreads();

        unsigned long long acc[4][4];
#pragma unroll
        for (int j = 0; j < 4; j++)
#pragma unroll
            for (int p = 0; p < 4; p++) acc[j][p] = 0ull;

        for (int tt = 0; tt < T; tt++) {
            int tz = tt / (ny * nx), rr = tt % (ny * nx), ty = rr / nx, tx = rr % nx;
            int kz = pz ? 1 : (tz ? 2 : 0);
            int ky = py ? 1 : (ty ? 2 : 0);
            int kx = px ? 1 : (tx ? 2 : 0);
            int k = (kz * 3 + ky) * 3 + kx;
            const ulonglong2* wp = (const ulonglong2*)&g_wI[k * 32 * COP + co0];
            const float* ap = &sact[(vg * 4) * ST + tt * 32];
#pragma unroll 4
            for (int ci = 0; ci < 32; ci++) {
                ulonglong2 w01 = __ldg(wp + ci * 32);       // COP floats = 32 u2
                ulonglong2 w23 = __ldg(wp + ci * 32 + 1);
#pragma unroll
                for (int j = 0; j < 4; j++) {
                    unsigned long long a2 = pk2(ap[j * ST + ci]);
                    fma2(acc[j][0], a2, w01.x);
                    fma2(acc[j][1], a2, w01.y);
                    fma2(acc[j][2], a2, w23.x);
                    fma2(acc[j][3], a2, w23.y);
                }
            }
        }

        float bv[8];
#pragma unroll
        for (int c = 0; c < 8; c++) bv[c] = (co0 + c < CO) ? __ldg(&binv[co0 + c]) : 0.f;

#pragma unroll
        for (int j = 0; j < 4; j++) {
            int v = vg * 4 + j;
            if (v < vc) {
                int enc = slist[v];
                int b = enc >> 21, z = (enc >> 14) & 127, y = (enc >> 7) & 127, x = enc & 127;
                size_t base = (size_t)b * CO * DDD + (size_t)z * DD + (size_t)y * DIN + x;
                float2 vv0 = upk(acc[j][0]), vv1 = upk(acc[j][1]);
                float2 vv2 = upk(acc[j][2]), vv3 = upk(acc[j][3]);
                float vals[8] = {vv0.x, vv0.y, vv1.x, vv1.y, vv2.x, vv2.y, vv3.x, vv3.y};
#pragma unroll
                for (int c = 0; c < 8; c++) {
                    int co = co0 + c;
                    if (co < CO) out[base + (size_t)co * DDD] = vals[c] + bv[c];
                }
            }
        }
        __syncthreads();
    }
}

// ---------------- launch ----------------
extern "C" void kernel_launch(void* const* d_in, const int* in_sizes, int n_in,
                              void* d_out, int out_size) {
    const float* x    = (const float*)d_in[0];
    const int*   m0   = (const int*)  d_in[1];
    const float* W1   = (const float*)d_in[2];
    const float* b1   = (const float*)d_in[3];
    const float* g1   = (const float*)d_in[4];
    const float* bt1  = (const float*)d_in[5];
    const float* rm1  = (const float*)d_in[6];
    const float* rv1  = (const float*)d_in[7];
    const float* W2   = (const float*)d_in[8];
    const float* b2   = (const float*)d_in[9];
    const float* g2   = (const float*)d_in[10];
    const float* bt2  = (const float*)d_in[11];
    const float* rm2  = (const float*)d_in[12];
    const float* rv2  = (const float*)d_in[13];
    const float* Winv = (const float*)d_in[14];
    const float* binv = (const float*)d_in[15];
    float* out = (float*)d_out;

    static cudaStream_t s2 = nullptr;
    static cudaEvent_t evA = nullptr, evB = nullptr;
    if (!s2) {
        cudaStreamCreateWithFlags(&s2, cudaStreamNonBlocking);
        cudaEventCreateWithFlags(&evA, cudaEventDisableTiming);
        cudaEventCreateWithFlags(&evB, cudaEventDisableTiming);
    }

    const int conv2_smem = 600 * CHP * 4;                     // 79200
    const int convinv_smem = 64 * (8 * 32 + 4) * 4 + 64 * 4;  // 66816
    cudaFuncSetAttribute(conv2_kernel, cudaFuncAttributeMaxDynamicSharedMemorySize,
                         conv2_smem);
    cudaFuncSetAttribute(convinv_kernel, cudaFuncAttributeMaxDynamicSharedMemorySize,
                         convinv_smem);

    prep_kernel<<<(27 * 32 * COP + 255) / 256, 256>>>(W1, b1, g1, bt1, rm1, rv1,
                                                      W2, b2, g2, bt2, rm2, rv2, Winv);

    // fork: big output memset + active-list build run concurrently with convs
    cudaEventRecord(evA, 0);
    cudaStreamWaitEvent(s2, evA, 0);
    cudaMemsetAsync(d_out, 0, (size_t)out_size * sizeof(float), s2);
    buildlist_kernel<<<(NB * DDD + 255) / 256, 256, 0, s2>>>(m0);
    cudaEventRecord(evB, s2);

    conv1_kernel<<<256, 256>>>(x, m0);
    conv2_kernel<<<256, 256, conv2_smem>>>();

    cudaStreamWaitEvent(0, evB, 0);
    dim3 g3(120, 8);
    convinv_kernel<<<g3, 256, convinv_smem>>>(out, binv);
}